// round 15
// baseline (speedup 1.0000x reference)
#include <cuda_runtime.h>
#include <cstdint>

// Problem constants
#define Bn 64
#define On 4000
#define Mn 128
#define Dn 64
#define TO 32           // opes per tile
#define TPB 125         // tiles per batch
#define G_TILES 8000
#define NC 444          // CTAs = 3/SM x 148, single wave at occ 3

// main smem (bytes): w-bf16 pp 2x8192 @0 | feat-bf16 pp 2x4096 @16384
// epilogue reuses floats: s_y[32*68] @0 | s_fm[32*68] @2176 | s_inv[32] @4352
#define SMEM_MAIN 24576

// ---------------- device scratch ----------------------------------------------
__device__ float g_vope[Dn];
__device__ float g_vmac[Dn];
__device__ float g_amac[Bn * Mn];
__device__ float g_part[(size_t)NC * 2 * Mn * Dn];   // 29 MB
__device__ float g_partZ[NC * 2 * Mn];
__device__ unsigned g_sync[Bn];                      // epilogue tickets

// ---------------- helpers ------------------------------------------------------
__device__ __forceinline__ void mma_bf16(float* c, uint32_t a0, uint32_t a1,
                                         uint32_t a2, uint32_t a3,
                                         uint32_t b0, uint32_t b1) {
    asm volatile(
        "mma.sync.aligned.m16n8k16.row.col.f32.bf16.bf16.f32 "
        "{%0,%1,%2,%3}, {%4,%5,%6,%7}, {%8,%9}, {%0,%1,%2,%3};"
        : "+f"(c[0]), "+f"(c[1]), "+f"(c[2]), "+f"(c[3])
        : "r"(a0), "r"(a1), "r"(a2), "r"(a3), "r"(b0), "r"(b1));
}
__device__ __forceinline__ void ldsm4t(uint32_t& r0, uint32_t& r1, uint32_t& r2,
                                       uint32_t& r3, uint32_t addr) {
    asm volatile("ldmatrix.sync.aligned.m8n8.x4.trans.shared.b16 {%0,%1,%2,%3}, [%4];"
                 : "=r"(r0), "=r"(r1), "=r"(r2), "=r"(r3) : "r"(addr));
}
__device__ __forceinline__ uint32_t pkbf(float lo, float hi) {
    uint32_t r;
    asm("cvt.rn.bf16x2.f32 %0, %1, %2;" : "=r"(r) : "f"(hi), "f"(lo));
    return r;
}

// ---------------- kernel 0: v_ope, v_mac, zero tickets --------------------------
__global__ void prep_kernel(const float* __restrict__ W_ope,
                            const float* __restrict__ alpha_ope,
                            const float* __restrict__ W_mac,
                            const float* __restrict__ alpha_mac) {
    int t = threadIdx.x;
    if (t < 64) {
        float s = 0.f;
#pragma unroll 8
        for (int k = 0; k < 64; ++k) s += alpha_ope[k] * W_ope[k * 64 + t];
        g_vope[t] = s;
        g_sync[t] = 0u;                 // reset tickets every replay
    } else {
        int d = t - 64;
        float s = 0.f;
#pragma unroll 8
        for (int k = 0; k < 64; ++k) s += alpha_mac[k] * W_mac[k * 64 + d];
        g_vmac[d] = s;
    }
}

// ---------------- kernel 1: a_mac ----------------------------------------------
__global__ void amac_kernel(const float* __restrict__ feat_mac) {
    int b = blockIdx.x, t = threadIdx.x;
    __shared__ float vs[64];
    if (t < 64) vs[t] = g_vmac[t];
    __syncthreads();
    const float4* fr = (const float4*)(feat_mac + ((size_t)b * Mn + t) * 64);
    float acc = 0.f;
#pragma unroll
    for (int j = 0; j < 16; ++j) {
        float4 f = __ldg(fr + j);
        acc += f.x * vs[4 * j] + f.y * vs[4 * j + 1] + f.z * vs[4 * j + 2] + f.w * vs[4 * j + 3];
    }
    g_amac[b * Mn + t] = acc;
}

// ---------------- kernel 2: main + fused ticket epilogue ------------------------
__global__ void __launch_bounds__(256, 3)
main_kernel(const float* __restrict__ proc, const float* __restrict__ feat,
            const float* __restrict__ feat_mac,
            const float* __restrict__ W_ope, const float* __restrict__ W_mac,
            float* __restrict__ out) {
    extern __shared__ float smem[];
    char* sm = (char*)smem;
    const uint32_t sbase = (uint32_t)__cvta_generic_to_shared(smem);
    __shared__ unsigned s_tick;

    const int cta = blockIdx.x;
    const int g0 = (int)(((long long)cta * G_TILES) / NC);
    const int g1 = (int)(((long long)(cta + 1) * G_TILES) / NC);
    const int n = g1 - g0;

    const int t = threadIdx.x, L = t & 31, wid = t >> 5;
    const int r = L >> 2, kq = L & 3;
    const int tau = L >> 3, rr = L & 7;

    float4 va = *(const float4*)(g_vope + (L & 7) * 8);
    float4 vb = *(const float4*)(g_vope + (L & 7) * 8 + 4);

    float cacc[9][4];
#pragma unroll
    for (int nn = 0; nn < 9; ++nn)
#pragma unroll
        for (int i = 0; i < 4; ++i) cacc[nn][i] = 0.f;

    float4 fA, fB;           // feat prefetch
    float4 p0, p1, p2, p3;   // proc prefetch

    auto LDGT = [&](int g) {
        if (g >= g1) return;
        const int bb = g / TPB;
        const int ob = (g % TPB) * TO;
        const float* fp = feat + ((size_t)bb * On + ob + wid + 8 * (L >> 3)) * 64
                        + (L & 7) * 8;
        fA = __ldg((const float4*)fp);
        fB = __ldg((const float4*)(fp + 4));
        const float* pp = proc + ((size_t)bb * On + ob) * 128 + 4 * L;
        p0 = __ldg((const float4*)(pp + (size_t)wid * 128));
        p1 = __ldg((const float4*)(pp + (size_t)(wid + 8) * 128));
        p2 = __ldg((const float4*)(pp + (size_t)(wid + 16) * 128));
        p3 = __ldg((const float4*)(pp + (size_t)(wid + 24) * 128));
    };

    auto STAGE = [&](int g, int pp) {
        const int bb = g / TPB;
        float4 am4 = __ldg((const float4*)(g_amac + bb * Mn + 4 * L));
        const int R = wid + 8 * (L >> 3);
        float pa = fA.x * va.x + fA.y * va.y + fA.z * va.z + fA.w * va.w
                 + fB.x * vb.x + fB.y * vb.y + fB.z * vb.z + fB.w * vb.w;
        pa += __shfl_xor_sync(0xFFFFFFFFu, pa, 1);
        pa += __shfl_xor_sync(0xFFFFFFFFu, pa, 2);
        pa += __shfl_xor_sync(0xFFFFFFFFu, pa, 4);
        uint4 fb4;
        fb4.x = pkbf(fA.x, fA.y); fb4.y = pkbf(fA.z, fA.w);
        fb4.z = pkbf(fB.x, fB.y); fb4.w = pkbf(fB.z, fB.w);
        *(uint4*)(sm + 16384 + pp * 4096 + R * 128 + (((L & 7) ^ (R & 7)) << 4)) = fb4;
        float4 pr[4] = {p0, p1, p2, p3};
#pragma unroll
        for (int j = 0; j < 4; ++j) {
            float a = __shfl_sync(0xFFFFFFFFu, pa, 8 * j);
            const int o = wid + 8 * j;
            float s0 = a + am4.x, s1 = a + am4.y, s2 = a + am4.z, s3 = a + am4.w;
            float w0 = (pr[j].x == 1.f) ? __expf(fmaxf(s0, 0.2f * s0)) : 0.f;
            float w1 = (pr[j].y == 1.f) ? __expf(fmaxf(s1, 0.2f * s1)) : 0.f;
            float w2 = (pr[j].z == 1.f) ? __expf(fmaxf(s2, 0.2f * s2)) : 0.f;
            float w3 = (pr[j].w == 1.f) ? __expf(fmaxf(s3, 0.2f * s3)) : 0.f;
            uint2 wp;
            wp.x = pkbf(w0, w1);
            wp.y = pkbf(w2, w3);
            *(uint2*)(sm + pp * 8192 + o * 256 +
                      (((L >> 1) ^ (o & 7)) << 4) + ((L & 1) << 3)) = wp;
        }
    };

    auto MMAF = [&](int pp) {
        const uint32_t wb = sbase + (uint32_t)pp * 8192u;
        const uint32_t fbB = sbase + 16384u + (uint32_t)pp * 4096u;
        const uint32_t addrA0 = wb + (uint32_t)(((((tau >> 1) << 3) + rr) << 8) +
                                     ((((2 * wid + (tau & 1)) ^ rr) & 15) << 4));
        const uint32_t addrB0 = fbB + (uint32_t)((((tau & 1) << 3) + rr) << 7);
        const uint32_t ones = 0x3F803F80u;
#pragma unroll
        for (int ks = 0; ks < 2; ++ks) {
            uint32_t a0, a1, a2, a3;
            ldsm4t(a0, a1, a2, a3, addrA0 + ks * 4096);
#pragma unroll
            for (int np = 0; np < 4; ++np) {
                uint32_t b0, b1, b2, b3;
                uint32_t chunk = (uint32_t)(((2 * np + (tau >> 1)) ^ rr) & 7);
                ldsm4t(b0, b1, b2, b3, addrB0 + ks * 2048 + (chunk << 4));
                mma_bf16(cacc[2 * np],     a0, a1, a2, a3, b0, b1);
                mma_bf16(cacc[2 * np + 1], a0, a1, a2, a3, b2, b3);
            }
            mma_bf16(cacc[8], a0, a1, a2, a3, ones, ones);   // Z tile
        }
    };

    int seg = 0;
    auto FLUSH = [&]() {
        float* pbase = g_part + ((size_t)(cta * 2 + seg) * Mn) * Dn;
        const int mA = 16 * wid + r, mB = mA + 8;
#pragma unroll
        for (int nn = 0; nn < 8; ++nn) {
            int d = 8 * nn + 2 * kq;
            float2 v0 = {cacc[nn][0], cacc[nn][1]};
            float2 v1 = {cacc[nn][2], cacc[nn][3]};
            *(float2*)(pbase + (size_t)mA * Dn + d) = v0;
            *(float2*)(pbase + (size_t)mB * Dn + d) = v1;
        }
        if (kq == 0) {
            g_partZ[(cta * 2 + seg) * Mn + mA] = cacc[8][0];
            g_partZ[(cta * 2 + seg) * Mn + mB] = cacc[8][2];
        }
#pragma unroll
        for (int nn = 0; nn < 9; ++nn)
#pragma unroll
            for (int i = 0; i < 4; ++i) cacc[nn][i] = 0.f;
        ++seg;
    };

    // ---- prologue ----
    LDGT(g0);
    STAGE(g0, 0);
    LDGT(g0 + 1);
    __syncthreads();

    // ---- main loop: one barrier per tile ----
    for (int lt = 0; lt < n; ++lt) {
        const int g = g0 + lt;
        if (lt + 1 < n) STAGE(g + 1, (lt + 1) & 1);
        LDGT(g + 2);
        MMAF(lt & 1);
        if (lt + 1 == n || (g + 1) % TPB == 0) FLUSH();
        __syncthreads();
    }

    // ================= fused epilogue (ticket-based) ============================
    __threadfence();          // make this CTA's partial stores globally visible
    __syncthreads();

    const int bbA = g0 / TPB, bbB = (g1 - 1) / TPB;
    for (int q2 = 0; q2 < 2; ++q2) {
        const int bb = q2 ? bbB : bbA;
        if (q2 == 1 && bbB == bbA) break;

        int i_lo = (int)(((long long)(TPB * bb)) * NC / G_TILES) - 1;
        int i_hi = (int)(((long long)(TPB * (bb + 1) - 1)) * NC / G_TILES) + 1;
        if (i_lo < 0) i_lo = 0;
        if (i_hi > NC - 1) i_hi = NC - 1;

        if (t == 0) {
            unsigned cnt = 0;
            for (int i = i_lo; i <= i_hi; ++i) {
                int gi0 = (int)(((long long)i * G_TILES) / NC);
                int gi1 = (int)(((long long)(i + 1) * G_TILES) / NC);
                if (bb == gi0 / TPB || bb == (gi1 - 1) / TPB) ++cnt;
            }
            unsigned old = atomicAdd(&g_sync[bb], 1u);
            s_tick = (old + 1u == cnt) ? 1u : 0u;
        }
        __syncthreads();

        if (s_tick) {       // this CTA is last for batch bb -> run its epilogue
            __threadfence();
            float* s_y   = smem;          // 32 x 68
            float* s_fm  = smem + 2176;   // 32 x 68
            float* s_inv = smem + 4352;   // 32
            for (int mq = 0; mq < 4; ++mq) {
                const int mbase = 32 * mq;
                // fm strip (coalesced)
#pragma unroll
                for (int i2 = 0; i2 < 2; ++i2) {
                    int q = t + 256 * i2;
                    int row = q >> 4, c = 4 * (q & 15);
                    *(float4*)(s_fm + row * 68 + c) = __ldg(
                        (const float4*)(feat_mac + ((size_t)bb * Mn + mbase + row) * 64 + c));
                }
                // combine partials (L2-coherent reads)
                const int ml = t >> 3;
                const int d0 = (t & 7) * 8;
                float4 a0 = {0, 0, 0, 0}, a1 = {0, 0, 0, 0};
                float z = 0.f;
                for (int i = i_lo; i <= i_hi; ++i) {
                    int gi0 = (int)(((long long)i * G_TILES) / NC);
                    int gi1 = (int)(((long long)(i + 1) * G_TILES) / NC);
                    int b0i = gi0 / TPB, b1i = (gi1 - 1) / TPB;
                    int sg;
                    if (bb == b0i) sg = 0;
                    else if (bb == b1i) sg = 1;
                    else continue;
                    const float* pb = g_part +
                        ((size_t)(i * 2 + sg) * Mn + mbase + ml) * Dn + d0;
                    float4 x0 = __ldcg((const float4*)pb);
                    float4 x1 = __ldcg((const float4*)(pb + 4));
                    a0.x += x0.x; a0.y += x0.y; a0.z += x0.z; a0.w += x0.w;
                    a1.x += x1.x; a1.y += x1.y; a1.z += x1.z; a1.w += x1.w;
                    if (t < 32) z += __ldcg(&g_partZ[(i * 2 + sg) * Mn + mbase + t]);
                }
                if (t < 32) s_inv[t] = (z > 0.f) ? (1.f / z) : 0.f;
                __syncthreads();
                {
                    float inv = s_inv[ml];
                    a0.x *= inv; a0.y *= inv; a0.z *= inv; a0.w *= inv;
                    a1.x *= inv; a1.y *= inv; a1.z *= inv; a1.w *= inv;
                    *(float4*)(s_y + ml * 68 + d0) = a0;
                    *(float4*)(s_y + ml * 68 + d0 + 4) = a1;
                }
                __syncthreads();
                // project: lane L = m-row, warp wid = k-octet; W via uniform ldg
                float accv[8] = {0.f, 0.f, 0.f, 0.f, 0.f, 0.f, 0.f, 0.f};
                const float* yr = s_y + L * 68;
                const float* fr2 = s_fm + L * 68;
#pragma unroll
                for (int j = 0; j < 16; ++j) {
                    float4 y4 = *(const float4*)(yr + 4 * j);
                    float4 f4 = *(const float4*)(fr2 + 4 * j);
#pragma unroll
                    for (int kk = 0; kk < 8; ++kk) {
                        float4 w4 = __ldg(
                            (const float4*)(W_ope + (size_t)(wid * 8 + kk) * 64 + 4 * j));
                        float4 wm4 = __ldg(
                            (const float4*)(W_mac + (size_t)(wid * 8 + kk) * 64 + 4 * j));
                        accv[kk] += y4.x * w4.x + y4.y * w4.y + y4.z * w4.z + y4.w * w4.w
                                  + f4.x * wm4.x + f4.y * wm4.y + f4.z * wm4.z + f4.w * wm4.w;
                    }
                }
                size_t ob = ((size_t)(bb * Mn) + mbase + L) * Dn + wid * 8;
                float4 o0 = {accv[0], accv[1], accv[2], accv[3]};
                float4 o1 = {accv[4], accv[5], accv[6], accv[7]};
                *(float4*)(out + ob) = o0;
                *(float4*)(out + ob + 4) = o1;
                __syncthreads();   // s_y/s_fm/s_inv reuse next strip
            }
        }
        __syncthreads();
    }
}

// ---------------- launch --------------------------------------------------------
extern "C" void kernel_launch(void* const* d_in, const int* in_sizes, int n_in,
                              void* d_out, int out_size) {
    const float* proc      = (const float*)d_in[0];
    const float* feat_ope  = (const float*)d_in[2];
    const float* feat_mac  = (const float*)d_in[3];
    const float* W_ope     = (const float*)d_in[4];
    const float* W_mac     = (const float*)d_in[5];
    const float* alpha_ope = (const float*)d_in[6];
    const float* alpha_mac = (const float*)d_in[7];
    float* out = (float*)d_out;

    static int smem_set = 0;
    if (!smem_set) {
        cudaFuncSetAttribute(main_kernel, cudaFuncAttributeMaxDynamicSharedMemorySize,
                             SMEM_MAIN);
        smem_set = 1;
    }

    prep_kernel<<<1, 128>>>(W_ope, alpha_ope, W_mac, alpha_mac);
    amac_kernel<<<Bn, 128>>>(feat_mac);
    main_kernel<<<NC, 256, SMEM_MAIN>>>(proc, feat_ope, feat_mac, W_ope, W_mac, out);
}

// round 16
// speedup vs baseline: 2.0820x; 2.0820x over previous
#include <cuda_runtime.h>
#include <cstdint>

// Problem constants
#define Bn 64
#define On 4000
#define Mn 128
#define Dn 64
#define TO 32           // opes per tile
#define TPB 125         // tiles per batch
#define G_TILES 8000
#define NC 444          // CTAs = 3/SM x 148, single wave at occ 3

// main smem (bytes): featf32 ring 3x8192 @0 | w-bf16 pp 2x8192 @24576 | feat-bf16 pp 2x4096 @40960
#define SMEM_MAIN 49152
// finish smem floats: W 4352 | Wm 4352 | y 4096 | fm 4096 | inv 64
#define FIN_SMEM  (16960 * 4)

// ---------------- device scratch ----------------------------------------------
__device__ float g_vope[Dn];
__device__ float g_amac[Bn * Mn];
__device__ float g_part[(size_t)NC * 2 * Mn * Dn];   // 29 MB
__device__ float g_partZ[NC * 2 * Mn];

// ---------------- helpers ------------------------------------------------------
__device__ __forceinline__ void mma_bf16(float* c, uint32_t a0, uint32_t a1,
                                         uint32_t a2, uint32_t a3,
                                         uint32_t b0, uint32_t b1) {
    asm volatile(
        "mma.sync.aligned.m16n8k16.row.col.f32.bf16.bf16.f32 "
        "{%0,%1,%2,%3}, {%4,%5,%6,%7}, {%8,%9}, {%0,%1,%2,%3};"
        : "+f"(c[0]), "+f"(c[1]), "+f"(c[2]), "+f"(c[3])
        : "r"(a0), "r"(a1), "r"(a2), "r"(a3), "r"(b0), "r"(b1));
}
__device__ __forceinline__ void ldsm4t(uint32_t& r0, uint32_t& r1, uint32_t& r2,
                                       uint32_t& r3, uint32_t addr) {
    asm volatile("ldmatrix.sync.aligned.m8n8.x4.trans.shared.b16 {%0,%1,%2,%3}, [%4];"
                 : "=r"(r0), "=r"(r1), "=r"(r2), "=r"(r3) : "r"(addr));
}
__device__ __forceinline__ uint32_t pkbf(float lo, float hi) {
    uint32_t r;
    asm("cvt.rn.bf16x2.f32 %0, %1, %2;" : "=r"(r) : "f"(hi), "f"(lo));
    return r;
}
__device__ __forceinline__ void cp16(uint32_t dst, const float* src) {
    asm volatile("cp.async.cg.shared.global [%0], [%1], 16;" :: "r"(dst), "l"(src));
}
__device__ __forceinline__ void cp_commit() { asm volatile("cp.async.commit_group;"); }
template <int N>
__device__ __forceinline__ void cp_wait() {
    asm volatile("cp.async.wait_group %0;" :: "n"(N));
}

// ---------------- kernel 0: fused prep + a_mac (64 blocks x 128 threads) --------
// Every block computes v_mac redundantly (fully unrolled; W_mac L2-hot).
// Block 0's threads 64..127 also compute v_ope. Then each block b computes
// a_mac[b, m] = feat_mac[b,m,:] . v_mac for its batch.
__global__ void prep_amac_kernel(const float* __restrict__ W_ope,
                                 const float* __restrict__ alpha_ope,
                                 const float* __restrict__ W_mac,
                                 const float* __restrict__ alpha_mac,
                                 const float* __restrict__ feat_mac) {
    const int b = blockIdx.x, t = threadIdx.x;
    __shared__ float vs[64];

    if (t < 64) {               // v_mac (redundant per block; fully unrolled)
        float s = 0.f;
#pragma unroll
        for (int k = 0; k < 64; ++k) s += __ldg(alpha_mac + k) * __ldg(W_mac + k * 64 + t);
        vs[t] = s;
    } else if (b == 0) {        // v_ope (block 0 only)
        const int d = t - 64;
        float s = 0.f;
#pragma unroll
        for (int k = 0; k < 64; ++k) s += __ldg(alpha_ope + k) * __ldg(W_ope + k * 64 + d);
        g_vope[d] = s;
    }
    __syncthreads();

    // a_mac: thread t = machine m
    const float4* fr = (const float4*)(feat_mac + ((size_t)b * Mn + t) * 64);
    float acc = 0.f;
#pragma unroll
    for (int j = 0; j < 16; ++j) {
        float4 f = __ldg(fr + j);
        acc += f.x * vs[4 * j] + f.y * vs[4 * j + 1] + f.z * vs[4 * j + 2] + f.w * vs[4 * j + 3];
    }
    g_amac[b * Mn + t] = acc;
}

// ---------------- kernel 1: main (bf16 mma + ldmatrix, proc in regs, occ 3) ----
// BYTE-IDENTICAL to the R11 74.2us version.
__global__ void __launch_bounds__(256, 3)
main_kernel(const float* __restrict__ proc, const float* __restrict__ feat) {
    extern __shared__ float smem[];
    char* sm = (char*)smem;
    const uint32_t sbase = (uint32_t)__cvta_generic_to_shared(smem);

    const int cta = blockIdx.x;
    const int g0 = (int)(((long long)cta * G_TILES) / NC);
    const int g1 = (int)(((long long)(cta + 1) * G_TILES) / NC);
    const int n = g1 - g0;

    const int t = threadIdx.x, L = t & 31, wid = t >> 5;
    const int r = L >> 2, kq = L & 3;
    const int tau = L >> 3, rr = L & 7;

    float4 va = *(const float4*)(g_vope + (L & 7) * 8);
    float4 vb = *(const float4*)(g_vope + (L & 7) * 8 + 4);

    float cacc[9][4];
#pragma unroll
    for (int nn = 0; nn < 9; ++nn)
#pragma unroll
        for (int i = 0; i < 4; ++i) cacc[nn][i] = 0.f;

    float4 p0, p1, p2, p3;   // proc prefetch registers (rows wid+{0,8,16,24})

    auto ISSUE = [&](int g) {
        if (g >= g1) return;
        const int bb = g / TPB;
        const int ob = (g % TPB) * TO;
        const float* featB = feat + ((size_t)bb * On + ob) * 64;
        const uint32_t fdst = sbase + (uint32_t)((g - g0) % 3) * 8192u;
#pragma unroll
        for (int i = 0; i < 2; ++i) {
            int c = 2 * t + i;
            int row = c >> 4, k = c & 15;
            int ks2 = k ^ ((row & 3) << 1);
            cp16(fdst + (row * 16 + ks2) * 16, featB + (size_t)row * 64 + k * 4);
        }
    };

    auto LDGP = [&](int g) {
        if (g >= g1) return;
        const int bb = g / TPB;
        const int ob = (g % TPB) * TO;
        const float* procB = proc + ((size_t)bb * On + ob) * 128 + 4 * L;
        p0 = __ldg((const float4*)(procB + (size_t)wid * 128));
        p1 = __ldg((const float4*)(procB + (size_t)(wid + 8) * 128));
        p2 = __ldg((const float4*)(procB + (size_t)(wid + 16) * 128));
        p3 = __ldg((const float4*)(procB + (size_t)(wid + 24) * 128));
    };

    auto STAGE = [&](int g, int pp) {
        const int fslot = (g - g0) % 3;
        const int bb = g / TPB;
        float4 am4 = __ldg((const float4*)(g_amac + bb * Mn + 4 * L));
        const float* Fs = smem + fslot * 2048;
        const int R = wid + 8 * (L >> 3);
        const int c0 = (2 * (L & 7)) ^ ((R & 3) << 1);
        float4 fA = *(const float4*)(Fs + R * 64 + c0 * 4);
        float4 fB = *(const float4*)(Fs + R * 64 + (c0 + 1) * 4);
        float pa = fA.x * va.x + fA.y * va.y + fA.z * va.z + fA.w * va.w
                 + fB.x * vb.x + fB.y * vb.y + fB.z * vb.z + fB.w * vb.w;
        pa += __shfl_xor_sync(0xFFFFFFFFu, pa, 1);
        pa += __shfl_xor_sync(0xFFFFFFFFu, pa, 2);
        pa += __shfl_xor_sync(0xFFFFFFFFu, pa, 4);
        uint4 fb4;
        fb4.x = pkbf(fA.x, fA.y); fb4.y = pkbf(fA.z, fA.w);
        fb4.z = pkbf(fB.x, fB.y); fb4.w = pkbf(fB.z, fB.w);
        *(uint4*)(sm + 40960 + pp * 4096 + R * 128 + (((L & 7) ^ (R & 7)) << 4)) = fb4;
        float4 pr[4] = {p0, p1, p2, p3};
#pragma unroll
        for (int j = 0; j < 4; ++j) {
            float a = __shfl_sync(0xFFFFFFFFu, pa, 8 * j);
            const int o = wid + 8 * j;
            float s0 = a + am4.x, s1 = a + am4.y, s2 = a + am4.z, s3 = a + am4.w;
            float w0 = (pr[j].x == 1.f) ? __expf(fmaxf(s0, 0.2f * s0)) : 0.f;
            float w1 = (pr[j].y == 1.f) ? __expf(fmaxf(s1, 0.2f * s1)) : 0.f;
            float w2 = (pr[j].z == 1.f) ? __expf(fmaxf(s2, 0.2f * s2)) : 0.f;
            float w3 = (pr[j].w == 1.f) ? __expf(fmaxf(s3, 0.2f * s3)) : 0.f;
            uint2 wp;
            wp.x = pkbf(w0, w1);
            wp.y = pkbf(w2, w3);
            *(uint2*)(sm + 24576 + pp * 8192 + o * 256 +
                      (((L >> 1) ^ (o & 7)) << 4) + ((L & 1) << 3)) = wp;
        }
    };

    auto MMAF = [&](int pp) {
        const uint32_t wb = sbase + 24576u + (uint32_t)pp * 8192u;
        const uint32_t fbB = sbase + 40960u + (uint32_t)pp * 4096u;
        const uint32_t addrA0 = wb + (uint32_t)(((((tau >> 1) << 3) + rr) << 8) +
                                     ((((2 * wid + (tau & 1)) ^ rr) & 15) << 4));
        const uint32_t addrB0 = fbB + (uint32_t)((((tau & 1) << 3) + rr) << 7);
        const uint32_t ones = 0x3F803F80u;   // bf16 {1.0, 1.0}
#pragma unroll
        for (int ks = 0; ks < 2; ++ks) {
            uint32_t a0, a1, a2, a3;
            ldsm4t(a0, a1, a2, a3, addrA0 + ks * 4096);
#pragma unroll
            for (int np = 0; np < 4; ++np) {
                uint32_t b0, b1, b2, b3;
                uint32_t chunk = (uint32_t)(((2 * np + (tau >> 1)) ^ rr) & 7);
                ldsm4t(b0, b1, b2, b3, addrB0 + ks * 2048 + (chunk << 4));
                mma_bf16(cacc[2 * np],     a0, a1, a2, a3, b0, b1);
                mma_bf16(cacc[2 * np + 1], a0, a1, a2, a3, b2, b3);
            }
            mma_bf16(cacc[8], a0, a1, a2, a3, ones, ones);   // Z tile
        }
    };

    int seg = 0;
    auto FLUSH = [&]() {
        float* pbase = g_part + ((size_t)(cta * 2 + seg) * Mn) * Dn;
        const int mA = 16 * wid + r, mB = mA + 8;
#pragma unroll
        for (int nn = 0; nn < 8; ++nn) {
            int d = 8 * nn + 2 * kq;
            float2 v0 = {cacc[nn][0], cacc[nn][1]};
            float2 v1 = {cacc[nn][2], cacc[nn][3]};
            *(float2*)(pbase + (size_t)mA * Dn + d) = v0;
            *(float2*)(pbase + (size_t)mB * Dn + d) = v1;
        }
        if (kq == 0) {
            g_partZ[(cta * 2 + seg) * Mn + mA] = cacc[8][0];
            g_partZ[(cta * 2 + seg) * Mn + mB] = cacc[8][2];
        }
#pragma unroll
        for (int nn = 0; nn < 9; ++nn)
#pragma unroll
            for (int i = 0; i < 4; ++i) cacc[nn][i] = 0.f;
        ++seg;
    };

    // ---- prologue ----
    ISSUE(g0); cp_commit();
    ISSUE(g0 + 1); cp_commit();
    LDGP(g0);
    cp_wait<1>();
    __syncthreads();
    STAGE(g0, 0);
    __syncthreads();

    for (int lt = 0; lt < n; ++lt) {
        const int g = g0 + lt;
        ISSUE(g + 2); cp_commit();
        LDGP(g + 1);
        MMAF(lt & 1);                  // overlaps cp.async for g+1
        cp_wait<1>();
        __syncthreads();               // featf32(g+1) visible
        if (lt + 1 < n) STAGE(g + 1, (lt + 1) & 1);
        if (lt + 1 == n || (g + 1) % TPB == 0) FLUSH();
        __syncthreads();               // staged w/fb visible; ring reuse safe
    }
}

// ---------------- kernel 2: combine + normalize + project + fused h_mac --------
// grid (Bn, 2): 64-m strip, 512 threads. BYTE-IDENTICAL to the R11 version.
__global__ void __launch_bounds__(512)
finish_kernel(const float* __restrict__ W_ope, const float* __restrict__ W_mac,
              const float* __restrict__ feat_mac, float* __restrict__ out) {
    extern __shared__ float fs[];
    float* s_W   = fs;                   // 64 x 68
    float* s_Wm  = fs + 4352;            // 64 x 68
    float* s_y   = fs + 8704;            // 64 x 64
    float* s_fm  = fs + 8704 + 4096;     // 64 x 64
    float* s_inv = fs + 8704 + 8192;     // 64

    const int b = blockIdx.x, mq = blockIdx.y;
    const int mbase = 64 * mq;
    const int t = threadIdx.x;
    const int k = t & 63, mr = t >> 6;   // mr 0..7

#pragma unroll
    for (int qq = 0; qq < 2; ++qq) {
        int q = t + 512 * qq;
        int kk = q >> 4, j = q & 15;
        *(float4*)(s_W + kk * 68 + 4 * j) = __ldg((const float4*)(W_ope + kk * 64 + 4 * j));
        *(float4*)(s_Wm + kk * 68 + 4 * j) = __ldg((const float4*)(W_mac + kk * 64 + 4 * j));
    }
#pragma unroll
    for (int qq = 0; qq < 2; ++qq) {
        int q = t + 512 * qq;
        int row = q >> 4, c = 4 * (q & 15);
        *(float4*)(s_fm + row * 64 + c) =
            __ldg((const float4*)(feat_mac + ((size_t)b * Mn + mbase + row) * 64 + c));
    }

    int i_lo = (int)(((long long)(TPB * b)) * NC / G_TILES) - 1;
    int i_hi = (int)(((long long)(TPB * (b + 1) - 1)) * NC / G_TILES) + 1;
    if (i_lo < 0) i_lo = 0;
    if (i_hi > NC - 1) i_hi = NC - 1;

    const int ml = t >> 3;            // combine: row ml (0..63), d = (t&7)*8
    const int d0 = (t & 7) * 8;
    float4 a0 = {0, 0, 0, 0}, a1 = {0, 0, 0, 0};
    float z = 0.f;
    for (int i = i_lo; i <= i_hi; ++i) {
        int gi0 = (int)(((long long)i * G_TILES) / NC);
        int gi1 = (int)(((long long)(i + 1) * G_TILES) / NC);
        int b0i = gi0 / TPB, b1i = (gi1 - 1) / TPB;
        int sg;
        if (b == b0i) sg = 0;
        else if (b == b1i) sg = 1;
        else continue;
        const float* pb = g_part + ((size_t)(i * 2 + sg) * Mn + mbase + ml) * Dn + d0;
        float4 x0 = __ldg((const float4*)pb);
        float4 x1 = __ldg((const float4*)(pb + 4));
        a0.x += x0.x; a0.y += x0.y; a0.z += x0.z; a0.w += x0.w;
        a1.x += x1.x; a1.y += x1.y; a1.z += x1.z; a1.w += x1.w;
        if (t < 64) z += g_partZ[(i * 2 + sg) * Mn + mbase + t];
    }
    if (t < 64) s_inv[t] = (z > 0.f) ? (1.f / z) : 0.f;
    __syncthreads();
    {
        float inv = s_inv[ml];
        a0.x *= inv; a0.y *= inv; a0.z *= inv; a0.w *= inv;
        a1.x *= inv; a1.y *= inv; a1.z *= inv; a1.w *= inv;
        *(float4*)(s_y + ml * 64 + d0) = a0;
        *(float4*)(s_y + ml * 64 + d0 + 4) = a1;
    }
    __syncthreads();

    float accv[8] = {0.f, 0.f, 0.f, 0.f, 0.f, 0.f, 0.f, 0.f};
#pragma unroll
    for (int j = 0; j < 16; ++j) {
        float4 wr = *(const float4*)(s_W + k * 68 + 4 * j);
        float4 wm = *(const float4*)(s_Wm + k * 68 + 4 * j);
#pragma unroll
        for (int i = 0; i < 8; ++i) {
            int mloc = mr * 8 + i;
            float4 y = *(const float4*)(s_y + mloc * 64 + 4 * j);
            float4 fm = *(const float4*)(s_fm + mloc * 64 + 4 * j);
            accv[i] += y.x * wr.x + y.y * wr.y + y.z * wr.z + y.w * wr.w
                     + fm.x * wm.x + fm.y * wm.y + fm.z * wm.z + fm.w * wm.w;
        }
    }
#pragma unroll
    for (int i = 0; i < 8; ++i)
        out[((size_t)(b * Mn) + mbase + mr * 8 + i) * Dn + k] = accv[i];
}

// ---------------- launch --------------------------------------------------------
extern "C" void kernel_launch(void* const* d_in, const int* in_sizes, int n_in,
                              void* d_out, int out_size) {
    const float* proc      = (const float*)d_in[0];
    const float* feat_ope  = (const float*)d_in[2];
    const float* feat_mac  = (const float*)d_in[3];
    const float* W_ope     = (const float*)d_in[4];
    const float* W_mac     = (const float*)d_in[5];
    const float* alpha_ope = (const float*)d_in[6];
    const float* alpha_mac = (const float*)d_in[7];
    float* out = (float*)d_out;

    static int smem_set = 0;
    if (!smem_set) {
        cudaFuncSetAttribute(main_kernel, cudaFuncAttributeMaxDynamicSharedMemorySize,
                             SMEM_MAIN);
        cudaFuncSetAttribute(finish_kernel, cudaFuncAttributeMaxDynamicSharedMemorySize,
                             FIN_SMEM);
        smem_set = 1;
    }

    prep_amac_kernel<<<Bn, 128>>>(W_ope, alpha_ope, W_mac, alpha_mac, feat_mac);
    main_kernel<<<NC, 256, SMEM_MAIN>>>(proc, feat_ope);
    finish_kernel<<<dim3(Bn, 2), 512, FIN_SMEM>>>(W_ope, W_mac, feat_mac, out);
}